// round 5
// baseline (speedup 1.0000x reference)
#include <cuda_runtime.h>
#include <cuda_bf16.h>
#include <cstdint>

// ---------------------------------------------------------------------------
// Problem dims (fixed)
// ---------------------------------------------------------------------------
#define BATCH   32
#define NPOS    1024
#define CH      512
#define MTOT    (BATCH * NPOS)
#define QKVN    (3 * CH)
#define GROUPS  8
#define CPG     (CH / GROUPS)
#define GN_ELEMS (NPOS * CPG)

// GEMM tiling: CTA 128x256, warp 64x64 (2x4 warps), BK=32, 4 stages
#define BM 128
#define BN 256
#define BK 32
#define KPAD 8
#define RS (BK + KPAD)              // 40 elems -> 80 B/row
#define STG_ROWS (BM + BN)          // 384 rows (A then B)
#define STG_ELEMS (STG_ROWS * RS)
#define STAGES 4
#define SMEM_BYTES (STAGES * STG_ELEMS * 2)   // 122880 B

// ---------------------------------------------------------------------------
// Scratch
// ---------------------------------------------------------------------------
__device__ __align__(256) __nv_bfloat16 g_h[(size_t)MTOT * CH];
__device__ __align__(256) __nv_bfloat16 g_wqkvT[(size_t)QKVN * CH];
__device__ __align__(256) __nv_bfloat16 g_wprojT[(size_t)CH * CH];
__device__ __align__(256) __nv_bfloat16 g_qkv[(size_t)MTOT * QKVN];
__device__ __align__(256) __nv_bfloat16 g_vT[(size_t)BATCH * CH * NPOS];
__device__ __align__(256) float         g_scores[(size_t)BATCH * NPOS * NPOS];
__device__ __align__(256) __nv_bfloat16 g_probs[(size_t)BATCH * NPOS * NPOS];
__device__ __align__(256) __nv_bfloat16 g_attn[(size_t)MTOT * CH];

// ---------------------------------------------------------------------------
// Helpers
// ---------------------------------------------------------------------------
__device__ __forceinline__ void cp16(uint32_t dst, const void* src) {
    asm volatile("cp.async.cg.shared.global [%0], [%1], 16;\n" :: "r"(dst), "l"(src));
}
__device__ __forceinline__ void ldm4(uint32_t& r0, uint32_t& r1, uint32_t& r2, uint32_t& r3,
                                     uint32_t addr) {
    asm volatile("ldmatrix.sync.aligned.m8n8.x4.shared.b16 {%0,%1,%2,%3}, [%4];\n"
                 : "=r"(r0), "=r"(r1), "=r"(r2), "=r"(r3) : "r"(addr));
}

// ---------------------------------------------------------------------------
// GroupNorm (vectorized)
// ---------------------------------------------------------------------------
__global__ __launch_bounds__(256) void groupnorm_kernel(
    const float* __restrict__ x, const float* __restrict__ gamma,
    const float* __restrict__ beta)
{
    const int b = blockIdx.x >> 3;
    const int grp = blockIdx.x & 7;
    const float* base = x + (size_t)b * NPOS * CH + grp * CPG;
    __nv_bfloat16* hout = g_h + (size_t)b * NPOS * CH + grp * CPG;
    const float4* base4 = (const float4*)base;

    float s = 0.f, s2 = 0.f;
    for (int idx = threadIdx.x; idx < GN_ELEMS / 4; idx += 256) {
        int n = idx >> 4, c4 = idx & 15;
        float4 v = base4[n * (CH / 4) + c4];
        s  += v.x + v.y + v.z + v.w;
        s2 += v.x * v.x + v.y * v.y + v.z * v.z + v.w * v.w;
    }
    __shared__ float red0[8], red1[8];
    #pragma unroll
    for (int o = 16; o; o >>= 1) {
        s  += __shfl_xor_sync(0xffffffffu, s, o);
        s2 += __shfl_xor_sync(0xffffffffu, s2, o);
    }
    if ((threadIdx.x & 31) == 0) { red0[threadIdx.x >> 5] = s; red1[threadIdx.x >> 5] = s2; }
    __syncthreads();
    float ts = 0.f, ts2 = 0.f;
    #pragma unroll
    for (int j = 0; j < 8; j++) { ts += red0[j]; ts2 += red1[j]; }
    const float inv_n = 1.f / (float)GN_ELEMS;
    float mean = ts * inv_n;
    float rstd = rsqrtf(ts2 * inv_n - mean * mean + 1e-3f);

    for (int idx = threadIdx.x; idx < GN_ELEMS / 4; idx += 256) {
        int n = idx >> 4, c4 = idx & 15;
        float4 v = base4[n * (CH / 4) + c4];
        int c = c4 * 4;
        float r0 = (v.x - mean) * rstd * gamma[grp * CPG + c]     + beta[grp * CPG + c];
        float r1 = (v.y - mean) * rstd * gamma[grp * CPG + c + 1] + beta[grp * CPG + c + 1];
        float r2 = (v.z - mean) * rstd * gamma[grp * CPG + c + 2] + beta[grp * CPG + c + 2];
        float r3 = (v.w - mean) * rstd * gamma[grp * CPG + c + 3] + beta[grp * CPG + c + 3];
        union { uint2 u; __nv_bfloat162 h2[2]; } pk;
        pk.h2[0] = __floats2bfloat162_rn(r0, r1);
        pk.h2[1] = __floats2bfloat162_rn(r2, r3);
        *(uint2*)&hout[n * CH + c] = pk.u;
    }
}

// ---------------------------------------------------------------------------
// Transposes
// ---------------------------------------------------------------------------
__global__ void transpose_w_kernel(const float* __restrict__ in,
                                   __nv_bfloat16* __restrict__ out,
                                   int R, int Ccol)
{
    __shared__ float tile[32][33];
    int c0 = blockIdx.x * 32, r0 = blockIdx.y * 32;
    int tx = threadIdx.x, ty = threadIdx.y;
    #pragma unroll
    for (int i = 0; i < 32; i += 8)
        tile[ty + i][tx] = in[(size_t)(r0 + ty + i) * Ccol + c0 + tx];
    __syncthreads();
    #pragma unroll
    for (int i = 0; i < 32; i += 8)
        out[(size_t)(c0 + ty + i) * R + r0 + tx] = __float2bfloat16_rn(tile[tx][ty + i]);
}

__global__ void transpose_v_kernel()
{
    __shared__ __nv_bfloat16 tile[32][33];
    int b = blockIdx.z;
    const __nv_bfloat16* in = g_qkv + (size_t)b * NPOS * QKVN + 2 * CH;
    __nv_bfloat16* out = g_vT + (size_t)b * CH * NPOS;
    int m0 = blockIdx.x * 32, c0 = blockIdx.y * 32;
    int tx = threadIdx.x, ty = threadIdx.y;
    #pragma unroll
    for (int i = 0; i < 32; i += 8)
        tile[ty + i][tx] = in[(size_t)(m0 + ty + i) * QKVN + c0 + tx];
    __syncthreads();
    #pragma unroll
    for (int i = 0; i < 32; i += 8)
        out[(size_t)(c0 + ty + i) * NPOS + m0 + tx] = tile[tx][ty + i];
}

// ---------------------------------------------------------------------------
// Softmax (vectorized)
// ---------------------------------------------------------------------------
__global__ __launch_bounds__(256) void softmax_kernel()
{
    const size_t row = blockIdx.x;
    const float4* s4 = (const float4*)(g_scores + row * NPOS);
    __nv_bfloat16* p = g_probs + row * NPOS;
    const int tid = threadIdx.x;
    __shared__ float red[8];

    float4 v = s4[tid];
    float mx = fmaxf(fmaxf(v.x, v.y), fmaxf(v.z, v.w));
    #pragma unroll
    for (int o = 16; o; o >>= 1) mx = fmaxf(mx, __shfl_xor_sync(0xffffffffu, mx, o));
    if ((tid & 31) == 0) red[tid >> 5] = mx;
    __syncthreads();
    mx = red[0];
    #pragma unroll
    for (int j = 1; j < 8; j++) mx = fmaxf(mx, red[j]);

    v.x = __expf(v.x - mx); v.y = __expf(v.y - mx);
    v.z = __expf(v.z - mx); v.w = __expf(v.w - mx);
    float sum = v.x + v.y + v.z + v.w;
    __syncthreads();
    #pragma unroll
    for (int o = 16; o; o >>= 1) sum += __shfl_xor_sync(0xffffffffu, sum, o);
    if ((tid & 31) == 0) red[tid >> 5] = sum;
    __syncthreads();
    float tot = 0.f;
    #pragma unroll
    for (int j = 0; j < 8; j++) tot += red[j];
    float rinv = 1.f / tot;
    union { uint2 u; __nv_bfloat162 h2[2]; } pk;
    pk.h2[0] = __floats2bfloat162_rn(v.x * rinv, v.y * rinv);
    pk.h2[1] = __floats2bfloat162_rn(v.z * rinv, v.w * rinv);
    *(uint2*)&p[tid * 4] = pk.u;
}

// ---------------------------------------------------------------------------
// NT bf16 GEMM: CTA 128x256, warp 64x64 (2x4), BK=32, 4-stage cp.async.
// C[M][N] = A[M][K] * B[N][K]^T.
// ---------------------------------------------------------------------------
template <int EPI>
__global__ __launch_bounds__(256, 1) void gemm_nt(
    const __nv_bfloat16* __restrict__ A, int lda, long long sA,
    const __nv_bfloat16* __restrict__ B, int ldb, long long sB,
    void* __restrict__ Cv, int ldc, long long sC,
    const float* __restrict__ bias, const float* __restrict__ resid,
    float scale, int K)
{
    extern __shared__ __nv_bfloat16 sm[];

    const int z = blockIdx.z;
    A += (size_t)z * sA;
    B += (size_t)z * sB;

    const int tid = threadIdx.x;
    const int wid = tid >> 5, lane = tid & 31;
    const int wm = wid >> 2, wn = wid & 3;     // 2 x 4 warps, each 64x64
    const int g = lane >> 2, t = lane & 3;
    const int m0 = blockIdx.y * BM;
    const int n0 = blockIdx.x * BN;

    const uint32_t s_base = (uint32_t)__cvta_generic_to_shared(sm);

    // ldmatrix lane mapping
    const int laneRow  = lane & 15;
    const int laneColH = (lane >> 4) * 8;
    const uint32_t aAddr0 = s_base + (((wm * 64 + laneRow) * RS + laneColH) << 1);
    const uint32_t bAddr0 = s_base + (((BM + wn * 64 + laneRow) * RS + laneColH) << 1);

    float acc[4][8][4] = {};

    const int kit = K / BK;

    // cp.async mapping: 6 chunks of 16B per thread (2 A rows-groups + 4 B)
#define LOAD_STAGE(st, ki) do {                                                     \
        int _k0 = (ki) * BK;                                                        \
        uint32_t _d = s_base + (st) * (STG_ELEMS * 2);                              \
        _Pragma("unroll")                                                           \
        for (int _i = 0; _i < 2; _i++) {                                            \
            int _id = tid + _i * 256;                                               \
            int _r = _id >> 2, _c = (_id & 3) * 8;                                  \
            cp16(_d + (_r * RS + _c) * 2, A + (size_t)(m0 + _r) * lda + _k0 + _c);  \
        }                                                                           \
        _Pragma("unroll")                                                           \
        for (int _i = 0; _i < 4; _i++) {                                            \
            int _id = tid + _i * 256;                                               \
            int _r = _id >> 2, _c = (_id & 3) * 8;                                  \
            cp16(_d + ((BM + _r) * RS + _c) * 2,                                    \
                 B + (size_t)(n0 + _r) * ldb + _k0 + _c);                           \
        }                                                                           \
        asm volatile("cp.async.commit_group;\n");                                   \
    } while (0)

    LOAD_STAGE(0, 0);
    LOAD_STAGE(1, 1);
    LOAD_STAGE(2, 2);

    for (int ki = 0; ki < kit; ki++) {
        asm volatile("cp.async.wait_group 2;\n");
        __syncthreads();

        // issue next stage first so it overlaps this iteration's MMA
        if (ki + 3 < kit) {
            LOAD_STAGE((ki + 3) & (STAGES - 1), ki + 3);
        } else {
            asm volatile("cp.async.commit_group;\n");
        }

        const int st = ki & (STAGES - 1);
        const uint32_t aoff = aAddr0 + st * (STG_ELEMS * 2);
        const uint32_t boff = bAddr0 + st * (STG_ELEMS * 2);

        #pragma unroll
        for (int kk = 0; kk < BK; kk += 16) {
            uint32_t af[4][4], bf[8][2];
            #pragma unroll
            for (int mi = 0; mi < 4; mi++)
                ldm4(af[mi][0], af[mi][1], af[mi][2], af[mi][3],
                     aoff + (mi * 16 * RS + kk) * 2);
            #pragma unroll
            for (int p = 0; p < 4; p++) {
                uint32_t q0, q1, q2, q3;
                ldm4(q0, q1, q2, q3, boff + (p * 16 * RS + kk) * 2);
                bf[2 * p][0] = q0; bf[2 * p + 1][0] = q1;
                bf[2 * p][1] = q2; bf[2 * p + 1][1] = q3;
            }
            #pragma unroll
            for (int mi = 0; mi < 4; mi++)
                #pragma unroll
                for (int ni = 0; ni < 8; ni++) {
                    asm volatile(
                        "mma.sync.aligned.m16n8k16.row.col.f32.bf16.bf16.f32 "
                        "{%0,%1,%2,%3}, {%4,%5,%6,%7}, {%8,%9}, {%0,%1,%2,%3};\n"
                        : "+f"(acc[mi][ni][0]), "+f"(acc[mi][ni][1]),
                          "+f"(acc[mi][ni][2]), "+f"(acc[mi][ni][3])
                        : "r"(af[mi][0]), "r"(af[mi][1]), "r"(af[mi][2]), "r"(af[mi][3]),
                          "r"(bf[ni][0]), "r"(bf[ni][1]));
                }
        }
    }
#undef LOAD_STAGE

    const size_t cbase = (size_t)z * sC;
    #pragma unroll
    for (int mi = 0; mi < 4; mi++) {
        #pragma unroll
        for (int ni = 0; ni < 8; ni++) {
            int row0 = m0 + wm * 64 + mi * 16 + g;
            int col  = n0 + wn * 64 + ni * 8 + t * 2;
            #pragma unroll
            for (int h2 = 0; h2 < 2; h2++) {
                int row = row0 + h2 * 8;
                float v0 = acc[mi][ni][h2 * 2 + 0];
                float v1 = acc[mi][ni][h2 * 2 + 1];
                size_t off = cbase + (size_t)row * ldc + col;
                if (EPI == 0) {
                    __nv_bfloat162 pk = __floats2bfloat162_rn(v0 + bias[col], v1 + bias[col + 1]);
                    *(__nv_bfloat162*)((__nv_bfloat16*)Cv + off) = pk;
                } else if (EPI == 1) {
                    *(float2*)((float*)Cv + off) = make_float2(v0 * scale, v1 * scale);
                } else if (EPI == 2) {
                    *(__nv_bfloat162*)((__nv_bfloat16*)Cv + off) = __floats2bfloat162_rn(v0, v1);
                } else {
                    float2 rx = *(const float2*)&resid[off];
                    *(float2*)((float*)Cv + off) =
                        make_float2(v0 + bias[col] + rx.x, v1 + bias[col + 1] + rx.y);
                }
            }
        }
    }
}

// ---------------------------------------------------------------------------
// Launch
// ---------------------------------------------------------------------------
extern "C" void kernel_launch(void* const* d_in, const int* in_sizes, int n_in,
                              void* d_out, int out_size)
{
    const float* x      = (const float*)d_in[0];
    const float* gamma  = (const float*)d_in[1];
    const float* beta   = (const float*)d_in[2];
    const float* w_qkv  = (const float*)d_in[3];
    const float* b_qkv  = (const float*)d_in[4];
    const float* w_proj = (const float*)d_in[5];
    const float* b_proj = (const float*)d_in[6];

    cudaFuncSetAttribute(gemm_nt<0>, cudaFuncAttributeMaxDynamicSharedMemorySize, SMEM_BYTES);
    cudaFuncSetAttribute(gemm_nt<1>, cudaFuncAttributeMaxDynamicSharedMemorySize, SMEM_BYTES);
    cudaFuncSetAttribute(gemm_nt<2>, cudaFuncAttributeMaxDynamicSharedMemorySize, SMEM_BYTES);
    cudaFuncSetAttribute(gemm_nt<3>, cudaFuncAttributeMaxDynamicSharedMemorySize, SMEM_BYTES);

    void *p_h, *p_wqkvT, *p_wprojT, *p_qkv, *p_vT, *p_scores, *p_probs, *p_attn;
    cudaGetSymbolAddress(&p_h, g_h);
    cudaGetSymbolAddress(&p_wqkvT, g_wqkvT);
    cudaGetSymbolAddress(&p_wprojT, g_wprojT);
    cudaGetSymbolAddress(&p_qkv, g_qkv);
    cudaGetSymbolAddress(&p_vT, g_vT);
    cudaGetSymbolAddress(&p_scores, g_scores);
    cudaGetSymbolAddress(&p_probs, g_probs);
    cudaGetSymbolAddress(&p_attn, g_attn);

    const __nv_bfloat16* hB      = (const __nv_bfloat16*)p_h;
    const __nv_bfloat16* wqkvTB  = (const __nv_bfloat16*)p_wqkvT;
    const __nv_bfloat16* wprojTB = (const __nv_bfloat16*)p_wprojT;
    const __nv_bfloat16* qkvB    = (const __nv_bfloat16*)p_qkv;
    const __nv_bfloat16* vTB     = (const __nv_bfloat16*)p_vT;
    const __nv_bfloat16* probsB  = (const __nv_bfloat16*)p_probs;
    const __nv_bfloat16* attnB   = (const __nv_bfloat16*)p_attn;

    transpose_w_kernel<<<dim3(QKVN / 32, CH / 32), dim3(32, 8)>>>(w_qkv, (__nv_bfloat16*)p_wqkvT, CH, QKVN);
    transpose_w_kernel<<<dim3(CH / 32, CH / 32), dim3(32, 8)>>>(w_proj, (__nv_bfloat16*)p_wprojT, CH, CH);
    groupnorm_kernel<<<BATCH * GROUPS, 256>>>(x, gamma, beta);

    // QKV: [32768,512] x [1536,512]^T
    gemm_nt<0><<<dim3(QKVN / BN, MTOT / BM, 1), 256, SMEM_BYTES>>>(
        hB, CH, 0, wqkvTB, CH, 0, p_qkv, QKVN, 0, b_qkv, nullptr, 0.f, CH);

    transpose_v_kernel<<<dim3(NPOS / 32, CH / 32, BATCH), dim3(32, 8)>>>();

    const float scale = 0.044194173824159216f; // 1/sqrt(512)
    gemm_nt<1><<<dim3(NPOS / BN, NPOS / BM, BATCH), 256, SMEM_BYTES>>>(
        qkvB, QKVN, (long long)NPOS * QKVN,
        qkvB + CH, QKVN, (long long)NPOS * QKVN,
        p_scores, NPOS, (long long)NPOS * NPOS,
        nullptr, nullptr, scale, CH);

    softmax_kernel<<<MTOT, 256>>>();

    gemm_nt<2><<<dim3(CH / BN, NPOS / BM, BATCH), 256, SMEM_BYTES>>>(
        probsB, NPOS, (long long)NPOS * NPOS,
        vTB, NPOS, (long long)CH * NPOS,
        p_attn, CH, (long long)NPOS * CH,
        nullptr, nullptr, 0.f, NPOS);

    gemm_nt<3><<<dim3(CH / BN, MTOT / BM, 1), 256, SMEM_BYTES>>>(
        attnB, CH, 0, wprojTB, CH, 0, d_out, CH, 0, b_proj, x, 0.f, CH);
}